// round 1
// baseline (speedup 1.0000x reference)
#include <cuda_runtime.h>
#include <cuda_fp16.h>

#define N_B 32
#define N_N 2048
#define N_D 16
#define N_C 64
#define N_E 32
#define NPART 37
#define SBCE (N_B * N_C * N_E)   // 65536

// Scratch (device globals; allocation-free kernel_launch)
__device__ __half g_u[(size_t)N_B * N_N * N_C * N_E];        // 256 MB fp16 predictions
__device__ float  g_partials[(size_t)NPART * SBCE];          // partial s sums
__device__ float  g_vsum[SBCE];                              // sum of v_j so far

__device__ __forceinline__ unsigned pack2(float a, float b) {
    __half2 h = __floats2half2_rn(a, b);
    return reinterpret_cast<unsigned&>(h);
}

// ---------------------------------------------------------------------------
// Kernel A: u = x*W + B (fp32 compute), store u as fp16, accumulate sum_n u
// grid (4 c-chunks, 37 n-blocks), 256 threads.
// Thread tile: 4 b x 1 c x 16 e.  W staged in smem with XOR swizzle.
// ---------------------------------------------------------------------------
__global__ __launch_bounds__(256, 1)
void capsA(const float* __restrict__ x, const float* __restrict__ W,
           const float* __restrict__ Bv)
{
    __shared__ float xs[N_B * N_D];    // 512 floats
    __shared__ float Ws[16 * 512];     // 16 c x 16 d x 32 e (swizzled)

    const int tid = threadIdx.x;
    const int cc  = blockIdx.x;            // c-chunk 0..3
    const int nb  = blockIdx.y;            // n-block 0..36
    const int c0  = cc * 16;
    const int ns  = (nb * N_N) / NPART;
    const int ne  = ((nb + 1) * N_N) / NPART;

    const int lane    = tid & 31;
    const int bq      = tid >> 5;          // 0..7 (b group of 4)
    const int c_local = lane >> 1;         // 0..15
    const int e0      = (lane & 1) * 16;   // 0 or 16
    const int swz     = (c_local & 7) << 2;

    // bias values for this thread's (c, e0..e0+15)
    float Bvals[16];
    #pragma unroll
    for (int j = 0; j < 16; j++)
        Bvals[j] = Bv[(c0 + c_local) * N_E + e0 + j];

    float sacc[4][16];
    #pragma unroll
    for (int i = 0; i < 4; i++)
        #pragma unroll
        for (int j = 0; j < 16; j++) sacc[i][j] = 0.0f;

    for (int n = ns; n < ne; n++) {
        __syncthreads();   // previous compute done; smem free for restage
        // stage x[:, n, :] (512 floats = 128 float4)
        if (tid < 128) {
            int b = tid >> 2, dq = tid & 3;
            float4 v = *reinterpret_cast<const float4*>(
                x + ((size_t)b * N_N + n) * N_D + dq * 4);
            *reinterpret_cast<float4*>(&xs[b * N_D + dq * 4]) = v;
        }
        // stage W[n, c0:c0+16, :, :] (8192 contiguous floats) with swizzle
        const float* Wn = W + (size_t)n * (N_C * N_D * N_E) + (size_t)c0 * (N_D * N_E);
        #pragma unroll
        for (int k = 0; k < 8; k++) {
            int q = tid + 256 * k;   // float4 index
            int p = q * 4;
            int cl = p >> 9;
            int rem = p & 511;
            int d = rem >> 5;
            int e = rem & 31;
            float4 v = *reinterpret_cast<const float4*>(Wn + p);
            int sw = (cl & 7) << 2;
            *reinterpret_cast<float4*>(&Ws[cl * 512 + d * 32 + (e ^ sw)]) = v;
        }
        __syncthreads();

        float uacc[4][16];
        #pragma unroll
        for (int i = 0; i < 4; i++)
            #pragma unroll
            for (int j = 0; j < 16; j++) uacc[i][j] = 0.0f;

        #pragma unroll
        for (int d = 0; d < N_D; d++) {
            float xv[4];
            #pragma unroll
            for (int i = 0; i < 4; i++)
                xv[i] = xs[(bq * 4 + i) * N_D + d];
            float wv[16];
            #pragma unroll
            for (int jq = 0; jq < 4; jq++) {
                float4 w = *reinterpret_cast<const float4*>(
                    &Ws[c_local * 512 + d * 32 + ((e0 + 4 * jq) ^ swz)]);
                wv[4 * jq + 0] = w.x; wv[4 * jq + 1] = w.y;
                wv[4 * jq + 2] = w.z; wv[4 * jq + 3] = w.w;
            }
            #pragma unroll
            for (int i = 0; i < 4; i++)
                #pragma unroll
                for (int j = 0; j < 16; j++)
                    uacc[i][j] = fmaf(xv[i], wv[j], uacc[i][j]);
        }

        // epilogue: +B, accumulate s1 partial, convert+store fp16 u
        #pragma unroll
        for (int i = 0; i < 4; i++) {
            int b = bq * 4 + i;
            float t[16];
            #pragma unroll
            for (int j = 0; j < 16; j++) {
                t[j] = uacc[i][j] + Bvals[j];
                sacc[i][j] += t[j];
            }
            uint4 lo = make_uint4(pack2(t[0], t[1]),  pack2(t[2], t[3]),
                                  pack2(t[4], t[5]),  pack2(t[6], t[7]));
            uint4 hi = make_uint4(pack2(t[8], t[9]),  pack2(t[10], t[11]),
                                  pack2(t[12], t[13]), pack2(t[14], t[15]));
            size_t uoff = (((size_t)b * N_N + n) * N_C + (c0 + c_local)) * N_E + e0;
            *reinterpret_cast<uint4*>(&g_u[uoff])     = lo;
            *reinterpret_cast<uint4*>(&g_u[uoff + 8]) = hi;
        }
    }

    // write partial sums (deterministic two-stage reduction)
    #pragma unroll
    for (int i = 0; i < 4; i++) {
        int b = bq * 4 + i;
        float* dst = &g_partials[(size_t)nb * SBCE +
                                 ((size_t)b * N_C + c0 + c_local) * N_E + e0];
        #pragma unroll
        for (int jq = 0; jq < 4; jq++) {
            float4 v = make_float4(sacc[i][4 * jq + 0], sacc[i][4 * jq + 1],
                                   sacc[i][4 * jq + 2], sacc[i][4 * jq + 3]);
            *reinterpret_cast<float4*>(dst + 4 * jq) = v;
        }
    }
}

// ---------------------------------------------------------------------------
// Kernel B: routing pass.  logits = u . vsum, coup = softmax_c, s += coup*u
// grid (32 b, 37 n-blocks), 256 threads.
// Thread: 4 c (cg, cg+16, cg+32, cg+48) x 1 e-pair.  Half-warp = one c-group.
// ---------------------------------------------------------------------------
__global__ __launch_bounds__(256, 8)
void capsB()
{
    __shared__ __half us[2][N_C * N_E];   // double-buffered u tile (2 x 4KB)
    __shared__ float  warp_sums[2][8];

    const int tid  = threadIdx.x;
    const int b    = blockIdx.x;
    const int nb   = blockIdx.y;
    const int ns   = (nb * N_N) / NPART;
    const int ne   = ((nb + 1) * N_N) / NPART;
    const int e2   = tid & 15;     // e-pair index
    const int cg   = tid >> 4;     // 0..15
    const int lane = tid & 31;
    const int wid  = tid >> 5;

    float vsr[4][2];
    #pragma unroll
    for (int k = 0; k < 4; k++) {
        int c = cg + 16 * k;
        const float* vp = g_vsum + ((size_t)b * N_C + c) * N_E + 2 * e2;
        vsr[k][0] = vp[0]; vsr[k][1] = vp[1];
    }
    float sacc[4][2];
    #pragma unroll
    for (int k = 0; k < 4; k++) { sacc[k][0] = 0.0f; sacc[k][1] = 0.0f; }

    // stage first tile
    {
        size_t base = ((size_t)b * N_N + ns) * (N_C * N_E);
        *reinterpret_cast<uint4*>(&us[0][tid * 8]) =
            *reinterpret_cast<const uint4*>(&g_u[base + tid * 8]);
    }

    for (int n = ns; n < ne; n++) {
        int cur = (n - ns) & 1;
        __syncthreads();   // us[cur] ready, warp_sums[cur] free

        float2 uf[4];
        #pragma unroll
        for (int k = 0; k < 4; k++) {
            __half2 h = *reinterpret_cast<const __half2*>(
                &us[cur][(cg + 16 * k) * N_E + 2 * e2]);
            uf[k] = __half22float2(h);
        }
        // prefetch next tile into the other buffer (overlaps compute)
        if (n + 1 < ne) {
            size_t base = ((size_t)b * N_N + (n + 1)) * (N_C * N_E);
            *reinterpret_cast<uint4*>(&us[cur ^ 1][tid * 8]) =
                *reinterpret_cast<const uint4*>(&g_u[base + tid * 8]);
        }

        // logits: dot over e, butterfly within half-warp (16 e-pair lanes)
        float lp[4];
        #pragma unroll
        for (int k = 0; k < 4; k++)
            lp[k] = uf[k].x * vsr[k][0] + uf[k].y * vsr[k][1];
        #pragma unroll
        for (int m = 1; m < 16; m <<= 1) {
            #pragma unroll
            for (int k = 0; k < 4; k++)
                lp[k] += __shfl_xor_sync(0xffffffffu, lp[k], m);
        }
        // softmax over c=64 (no max-sub needed: |logit| <= ~9)
        float ex[4], ploc = 0.0f;
        #pragma unroll
        for (int k = 0; k < 4; k++) { ex[k] = __expf(lp[k]); ploc += ex[k]; }
        #pragma unroll
        for (int m = 16; m >= 1; m >>= 1)
            ploc += __shfl_xor_sync(0xffffffffu, ploc, m);
        if (lane == 0) warp_sums[cur][wid] = ploc;
        __syncthreads();
        float tot = 0.0f;
        #pragma unroll
        for (int w = 0; w < 8; w++) tot += warp_sums[cur][w];
        // block total counts each c 16x (replicated across e-pair lanes)
        float inv = 16.0f / tot;
        #pragma unroll
        for (int k = 0; k < 4; k++) {
            float cp = ex[k] * inv;
            sacc[k][0] = fmaf(cp, uf[k].x, sacc[k][0]);
            sacc[k][1] = fmaf(cp, uf[k].y, sacc[k][1]);
        }
    }

    // write partials
    #pragma unroll
    for (int k = 0; k < 4; k++) {
        int c = cg + 16 * k;
        float2 v = make_float2(sacc[k][0], sacc[k][1]);
        *reinterpret_cast<float2*>(
            &g_partials[(size_t)nb * SBCE + ((size_t)b * N_C + c) * N_E + 2 * e2]) = v;
    }
}

// ---------------------------------------------------------------------------
// reduce partials (fixed order -> deterministic) + squash; update vsum
// grid 2048 (b,c pairs), 32 threads (lane = e)
// ---------------------------------------------------------------------------
__global__ void reduce_squash(float scale, int overwrite, float* __restrict__ out)
{
    int bc = blockIdx.x;     // b*64 + c
    int e  = threadIdx.x;
    size_t idx = (size_t)bc * N_E + e;
    float s = 0.0f;
    #pragma unroll
    for (int p = 0; p < NPART; p++)
        s += g_partials[(size_t)p * SBCE + idx];
    s *= scale;
    float nsq = s * s;
    #pragma unroll
    for (int m = 16; m >= 1; m >>= 1)
        nsq += __shfl_xor_sync(0xffffffffu, nsq, m);
    float sc = nsq / ((1.0f + nsq) * sqrtf(nsq + 1e-9f));
    float v = sc * s;
    if (overwrite) g_vsum[idx] = v;
    else           g_vsum[idx] += v;
    if (out) out[idx] = v;
}

// ---------------------------------------------------------------------------
extern "C" void kernel_launch(void* const* d_in, const int* in_sizes, int n_in,
                              void* d_out, int out_size)
{
    const float* x  = (const float*)d_in[0];
    const float* W  = (const float*)d_in[1];
    const float* Bv = (const float*)d_in[2];
    float* out = (float*)d_out;

    dim3 gA(4, NPART);
    dim3 gB(N_B, NPART);

    // pass 1: compute u (store fp16), s1 = sum_n u; coup uniform 1/64
    capsA<<<gA, 256>>>(x, W, Bv);
    reduce_squash<<<N_B * N_C, 32>>>(1.0f / 64.0f, 1, nullptr);   // v1 -> vsum
    // pass 2: logits = u.v1
    capsB<<<gB, 256>>>();
    reduce_squash<<<N_B * N_C, 32>>>(1.0f, 0, nullptr);           // vsum += v2
    // pass 3: logits = u.(v1+v2); final v3 -> d_out
    capsB<<<gB, 256>>>();
    reduce_squash<<<N_B * N_C, 32>>>(1.0f, 0, out);
}

// round 2
// speedup vs baseline: 1.2027x; 1.2027x over previous
#include <cuda_runtime.h>
#include <cuda_fp16.h>

#define N_B 32
#define N_N 2048
#define N_D 16
#define N_C 64
#define N_E 32
#define NPART 37
#define SBCE (N_B * N_C * N_E)   // 65536

typedef unsigned long long ull;

// Scratch (device globals; allocation-free kernel_launch)
__device__ __half g_u[(size_t)N_B * N_N * N_C * N_E];        // 256 MB fp16 predictions
__device__ float  g_partials[(size_t)NPART * SBCE];          // partial s sums
__device__ float  g_vsum[SBCE];                              // sum of v_j so far

// ---- packed f32x2 helpers (PTX ISA 8.7, sm_100+) ----
__device__ __forceinline__ ull ffma2(ull a, ull b, ull c) {
    ull d;
    asm("fma.rn.f32x2 %0, %1, %2, %3;" : "=l"(d) : "l"(a), "l"(b), "l"(c));
    return d;
}
__device__ __forceinline__ ull fadd2(ull a, ull b) {
    ull d;
    asm("add.rn.f32x2 %0, %1, %2;" : "=l"(d) : "l"(a), "l"(b));
    return d;
}
__device__ __forceinline__ ull fpack2(float lo, float hi) {
    ull d;
    asm("mov.b64 %0, {%1, %2};" : "=l"(d) : "f"(lo), "f"(hi));
    return d;
}
__device__ __forceinline__ float2 funpack2(ull v) {
    float2 f;
    asm("mov.b64 {%0, %1}, %2;" : "=f"(f.x), "=f"(f.y) : "l"(v));
    return f;
}

// ---- cp.async helpers ----
__device__ __forceinline__ void cp16(void* smem_dst, const void* gmem_src) {
    unsigned s = (unsigned)__cvta_generic_to_shared(smem_dst);
    asm volatile("cp.async.cg.shared.global [%0], [%1], 16;" :: "r"(s), "l"(gmem_src));
}
__device__ __forceinline__ void cp_commit() {
    asm volatile("cp.async.commit_group;");
}
__device__ __forceinline__ void cp_wait1() {
    asm volatile("cp.async.wait_group 1;" ::: "memory");
}

__global__ void nopk() {}   // launch-index padding so ncu -s 5 captures capsA

// ---------------------------------------------------------------------------
// Kernel A: u = x*W + B via packed f32x2 FFMA, store u fp16, accumulate sum_n u
// grid (8 c-chunks, 37 n-blocks) = 296 blocks (2/SM), 256 threads.
// Thread tile: 4 b x 1 c x 4 e-pairs (8 e).  cp.async double-buffered staging.
// ---------------------------------------------------------------------------
__global__ __launch_bounds__(256, 2)
void capsA(const float* __restrict__ x, const float* __restrict__ W,
           const float* __restrict__ Bv)
{
    __shared__ float xs[2][N_B * N_D];    // 2 x 2KB
    __shared__ float Ws[2][8 * 512];      // 2 x 16KB (8 c x 16 d x 32 e, swizzled)

    const int tid = threadIdx.x;
    const int cc  = blockIdx.x;            // c-chunk 0..7
    const int nb  = blockIdx.y;            // n-block 0..36
    const int c0  = cc * 8;
    const int ns  = (nb * N_N) / NPART;
    const int ne  = ((nb + 1) * N_N) / NPART;

    const int lane    = tid & 31;
    const int bq      = tid >> 5;          // 0..7 (b group of 4)
    const int c_local = lane >> 2;         // 0..7
    const int a       = lane & 3;          // e-octet selector: e base = 8*a
    const int swz4    = c_local & 7;       // float4-granularity swizzle
    const int c       = c0 + c_local;
    const int e_base  = 8 * a;

    // bias pairs for this thread's (c, e_base..e_base+7)
    ull Bv2[4];
    #pragma unroll
    for (int j = 0; j < 4; j++)
        Bv2[j] = fpack2(Bv[c * N_E + e_base + 2 * j],
                        Bv[c * N_E + e_base + 2 * j + 1]);

    ull sacc[4][4];
    #pragma unroll
    for (int i = 0; i < 4; i++)
        #pragma unroll
        for (int j = 0; j < 4; j++) sacc[i][j] = 0ull;

    // ---- staging lambda (cp.async) ----
    auto stage = [&](int n, int buf) {
        // W[n, c0:c0+8, :, :] = 4096 floats = 1024 float4, 4 per thread
        const float* Wn = W + (size_t)n * (N_C * N_D * N_E) + (size_t)c0 * (N_D * N_E);
        #pragma unroll
        for (int k = 0; k < 4; k++) {
            int q = tid + 256 * k;         // float4 index 0..1023
            int p = q * 4;                 // float index
            int cl = p >> 9;               // 0..7
            int d  = (p >> 5) & 15;
            int e4 = (p & 31) >> 2;        // float4 within e-row
            float* dst = &Ws[buf][cl * 512 + d * 32 + ((e4 ^ (cl & 7)) << 2)];
            cp16(dst, Wn + p);
        }
        // x[:, n, :] = 512 floats = 128 float4
        if (tid < 128) {
            int b = tid >> 2, dq = tid & 3;
            cp16(&xs[buf][b * N_D + dq * 4],
                 x + ((size_t)b * N_N + n) * N_D + dq * 4);
        }
        cp_commit();
    };

    stage(ns, 0);

    for (int n = ns; n < ne; n++) {
        int cur = (n - ns) & 1;
        if (n + 1 < ne) stage(n + 1, cur ^ 1);
        else            cp_commit();       // empty group keeps wait_group math right
        cp_wait1();
        __syncthreads();                   // data for n visible to all

        ull uacc[4][4];
        #pragma unroll
        for (int i = 0; i < 4; i++)
            #pragma unroll
            for (int j = 0; j < 4; j++) uacc[i][j] = 0ull;

        const float* Wrow = &Ws[cur][c_local * 512];
        #pragma unroll
        for (int d = 0; d < N_D; d++) {
            ull xv[4];
            #pragma unroll
            for (int i = 0; i < 4; i++) {
                float xval = xs[cur][(bq * 4 + i) * N_D + d];
                xv[i] = fpack2(xval, xval);
            }
            int o0 = (((2 * a + 0) ^ swz4) << 2) + d * 32;
            int o1 = (((2 * a + 1) ^ swz4) << 2) + d * 32;
            ulonglong2 w01 = *reinterpret_cast<const ulonglong2*>(Wrow + o0);
            ulonglong2 w23 = *reinterpret_cast<const ulonglong2*>(Wrow + o1);
            ull wv[4] = { w01.x, w01.y, w23.x, w23.y };
            #pragma unroll
            for (int i = 0; i < 4; i++)
                #pragma unroll
                for (int j = 0; j < 4; j++)
                    uacc[i][j] = ffma2(xv[i], wv[j], uacc[i][j]);
        }

        // epilogue: +B, accumulate s1 partial, convert+store fp16 u
        #pragma unroll
        for (int i = 0; i < 4; i++) {
            int b = bq * 4 + i;
            unsigned h[4];
            #pragma unroll
            for (int j = 0; j < 4; j++) {
                ull t = fadd2(uacc[i][j], Bv2[j]);
                sacc[i][j] = fadd2(sacc[i][j], t);
                float2 tf = funpack2(t);
                __half2 hh = __floats2half2_rn(tf.x, tf.y);
                h[j] = reinterpret_cast<unsigned&>(hh);
            }
            size_t uoff = (((size_t)b * N_N + n) * N_C + c) * N_E + e_base;
            *reinterpret_cast<uint4*>(&g_u[uoff]) = make_uint4(h[0], h[1], h[2], h[3]);
        }
        __syncthreads();                   // all done with buffer cur -> may be refilled
    }

    // write partial sums (deterministic two-stage reduction)
    #pragma unroll
    for (int i = 0; i < 4; i++) {
        int b = bq * 4 + i;
        ull* dst = reinterpret_cast<ull*>(
            &g_partials[(size_t)nb * SBCE + ((size_t)b * N_C + c) * N_E + e_base]);
        ulonglong2 v0 = make_ulonglong2(sacc[i][0], sacc[i][1]);
        ulonglong2 v1 = make_ulonglong2(sacc[i][2], sacc[i][3]);
        *reinterpret_cast<ulonglong2*>(dst)     = v0;
        *reinterpret_cast<ulonglong2*>(dst + 2) = v1;
    }
}

// ---------------------------------------------------------------------------
// Kernel B: routing pass.  logits = u . vsum, coup = softmax_c, s += coup*u
// grid (32 b, 37 n-blocks), 256 threads.  cp.async double-buffered u tiles.
// Thread: 4 c (cg, cg+16, cg+32, cg+48) x 1 e-pair.  Half-warp = one c-group.
// ---------------------------------------------------------------------------
__global__ __launch_bounds__(256, 8)
void capsB()
{
    __shared__ __half us[2][N_C * N_E];   // double-buffered u tile (2 x 4KB)
    __shared__ float  warp_sums[2][8];

    const int tid  = threadIdx.x;
    const int b    = blockIdx.x;
    const int nb   = blockIdx.y;
    const int ns   = (nb * N_N) / NPART;
    const int ne   = ((nb + 1) * N_N) / NPART;
    const int e2   = tid & 15;     // e-pair index
    const int cg   = tid >> 4;     // 0..15
    const int lane = tid & 31;
    const int wid  = tid >> 5;

    float vsr[4][2];
    #pragma unroll
    for (int k = 0; k < 4; k++) {
        int c = cg + 16 * k;
        const float* vp = g_vsum + ((size_t)b * N_C + c) * N_E + 2 * e2;
        vsr[k][0] = vp[0]; vsr[k][1] = vp[1];
    }
    float sacc[4][2];
    #pragma unroll
    for (int k = 0; k < 4; k++) { sacc[k][0] = 0.0f; sacc[k][1] = 0.0f; }

    // stage first tile via cp.async
    {
        size_t base = ((size_t)b * N_N + ns) * (N_C * N_E);
        cp16(&us[0][tid * 8], &g_u[base + tid * 8]);
        cp_commit();
    }

    for (int n = ns; n < ne; n++) {
        int cur = (n - ns) & 1;
        // prefetch next tile (buffer safety: guarded by trailing sync of prev iter)
        if (n + 1 < ne) {
            size_t base = ((size_t)b * N_N + (n + 1)) * (N_C * N_E);
            cp16(&us[cur ^ 1][tid * 8], &g_u[base + tid * 8]);
        }
        cp_commit();
        cp_wait1();
        __syncthreads();   // us[cur] ready for all, warp_sums[cur] free

        float2 uf[4];
        #pragma unroll
        for (int k = 0; k < 4; k++) {
            __half2 h = *reinterpret_cast<const __half2*>(
                &us[cur][(cg + 16 * k) * N_E + 2 * e2]);
            uf[k] = __half22float2(h);
        }

        // logits: dot over e, butterfly within half-warp (16 e-pair lanes)
        float lp[4];
        #pragma unroll
        for (int k = 0; k < 4; k++)
            lp[k] = uf[k].x * vsr[k][0] + uf[k].y * vsr[k][1];
        #pragma unroll
        for (int m = 1; m < 16; m <<= 1) {
            #pragma unroll
            for (int k = 0; k < 4; k++)
                lp[k] += __shfl_xor_sync(0xffffffffu, lp[k], m);
        }
        // softmax over c=64 (no max-sub needed: |logit| <= ~9)
        float ex[4], ploc = 0.0f;
        #pragma unroll
        for (int k = 0; k < 4; k++) { ex[k] = __expf(lp[k]); ploc += ex[k]; }
        #pragma unroll
        for (int m = 16; m >= 1; m >>= 1)
            ploc += __shfl_xor_sync(0xffffffffu, ploc, m);
        if (lane == 0) warp_sums[cur][wid] = ploc;
        __syncthreads();
        float tot = 0.0f;
        #pragma unroll
        for (int w = 0; w < 8; w++) tot += warp_sums[cur][w];
        // block total counts each c 16x (replicated across e-pair lanes)
        float inv = 16.0f / tot;
        #pragma unroll
        for (int k = 0; k < 4; k++) {
            float cp = ex[k] * inv;
            sacc[k][0] = fmaf(cp, uf[k].x, sacc[k][0]);
            sacc[k][1] = fmaf(cp, uf[k].y, sacc[k][1]);
        }
    }

    // write partials
    #pragma unroll
    for (int k = 0; k < 4; k++) {
        int c = cg + 16 * k;
        float2 v = make_float2(sacc[k][0], sacc[k][1]);
        *reinterpret_cast<float2*>(
            &g_partials[(size_t)nb * SBCE + ((size_t)b * N_C + c) * N_E + 2 * e2]) = v;
    }
}

// ---------------------------------------------------------------------------
// reduce partials (fixed order -> deterministic) + squash; update vsum
// grid 2048 (b,c pairs), 32 threads (lane = e)
// ---------------------------------------------------------------------------
__global__ void reduce_squash(float scale, int overwrite, float* __restrict__ out)
{
    int bc = blockIdx.x;     // b*64 + c
    int e  = threadIdx.x;
    size_t idx = (size_t)bc * N_E + e;
    float s = 0.0f;
    #pragma unroll
    for (int p = 0; p < NPART; p++)
        s += g_partials[(size_t)p * SBCE + idx];
    s *= scale;
    float nsq = s * s;
    #pragma unroll
    for (int m = 16; m >= 1; m >>= 1)
        nsq += __shfl_xor_sync(0xffffffffu, nsq, m);
    float sc = nsq / ((1.0f + nsq) * sqrtf(nsq + 1e-9f));
    float v = sc * s;
    if (overwrite) g_vsum[idx] = v;
    else           g_vsum[idx] += v;
    if (out) out[idx] = v;
}

// ---------------------------------------------------------------------------
extern "C" void kernel_launch(void* const* d_in, const int* in_sizes, int n_in,
                              void* d_out, int out_size)
{
    const float* x  = (const float*)d_in[0];
    const float* W  = (const float*)d_in[1];
    const float* Bv = (const float*)d_in[2];
    float* out = (float*)d_out;

    dim3 gA(8, NPART);
    dim3 gB(N_B, NPART);

    // 5 padding launches so ncu (-s 5 -c 1) profiles capsA
    for (int i = 0; i < 5; i++) nopk<<<1, 32>>>();

    // pass 1: compute u (store fp16), s1 = sum_n u; coup uniform 1/64
    capsA<<<gA, 256>>>(x, W, Bv);
    reduce_squash<<<N_B * N_C, 32>>>(1.0f / 64.0f, 1, nullptr);   // v1 -> vsum
    // pass 2: logits = u.v1
    capsB<<<gB, 256>>>();
    reduce_squash<<<N_B * N_C, 32>>>(1.0f, 0, nullptr);           // vsum += v2
    // pass 3: logits = u.(v1+v2); final v3 -> d_out
    capsB<<<gB, 256>>>();
    reduce_squash<<<N_B * N_C, 32>>>(1.0f, 0, out);
}

// round 5
// speedup vs baseline: 1.7105x; 1.4222x over previous
#include <cuda_runtime.h>
#include <cuda_fp16.h>

#define N_B 32
#define N_N 2048
#define N_D 16
#define N_C 64
#define N_E 32
#define NPART 37
#define SBCE (N_B * N_C * N_E)   // 65536

typedef unsigned long long ull;

// Scratch (device globals; allocation-free kernel_launch)
__device__ __half g_u[(size_t)N_B * N_N * N_C * N_E];        // 256 MB fp16 predictions
__device__ float  g_partials[(size_t)NPART * SBCE];          // partial s sums
__device__ float  g_vsum[SBCE];                              // sum of v_j so far

// ---- packed f32x2 helpers (sm_100+) ----
__device__ __forceinline__ ull ffma2(ull a, ull b, ull c) {
    ull d;
    asm("fma.rn.f32x2 %0, %1, %2, %3;" : "=l"(d) : "l"(a), "l"(b), "l"(c));
    return d;
}
__device__ __forceinline__ ull fadd2(ull a, ull b) {
    ull d;
    asm("add.rn.f32x2 %0, %1, %2;" : "=l"(d) : "l"(a), "l"(b));
    return d;
}
__device__ __forceinline__ ull fpack2(float lo, float hi) {
    ull d;
    asm("mov.b64 %0, {%1, %2};" : "=l"(d) : "f"(lo), "f"(hi));
    return d;
}
__device__ __forceinline__ float2 funpack2(ull v) {
    float2 f;
    asm("mov.b64 {%0, %1}, %2;" : "=f"(f.x), "=f"(f.y) : "l"(v));
    return f;
}

// ---- cp.async helpers ----
__device__ __forceinline__ void cp16(void* smem_dst, const void* gmem_src) {
    unsigned s = (unsigned)__cvta_generic_to_shared(smem_dst);
    asm volatile("cp.async.cg.shared.global [%0], [%1], 16;" :: "r"(s), "l"(gmem_src));
}
__device__ __forceinline__ void cp_commit() {
    asm volatile("cp.async.commit_group;");
}
__device__ __forceinline__ void cp_wait1() {
    asm volatile("cp.async.wait_group 1;" ::: "memory");
}
__device__ __forceinline__ void cp_wait2() {
    asm volatile("cp.async.wait_group 2;" ::: "memory");
}

// capsA dynamic smem layout: Ws[3][4096] floats, then xs[3][512] floats
#define CAPSA_WS_FLOATS (3 * 4096)
#define CAPSA_XS_FLOATS (3 * 512)
#define CAPSA_SMEM_BYTES ((CAPSA_WS_FLOATS + CAPSA_XS_FLOATS) * 4)

// ---------------------------------------------------------------------------
// Kernel A: u = x*W + B via packed f32x2 FFMA, store u fp16, accumulate sum_n u
// grid (8 c-chunks, 37 n-blocks) = 296 blocks (2/SM), 256 threads.
// Thread tile: 4 b x 1 c x 4 e-pairs.  3-stage cp.async pipeline (dynamic smem).
// ---------------------------------------------------------------------------
__global__ __launch_bounds__(256, 2)
void capsA(const float* __restrict__ x, const float* __restrict__ W,
           const float* __restrict__ Bv)
{
    extern __shared__ float smem[];
    float* Wsm = smem;                        // [3][4096]
    float* xsm = smem + CAPSA_WS_FLOATS;      // [3][512]

    const int tid = threadIdx.x;
    const int cc  = blockIdx.x;            // c-chunk 0..7
    const int nb  = blockIdx.y;            // n-block 0..36
    const int c0  = cc * 8;
    const int ns  = (nb * N_N) / NPART;
    const int ne  = ((nb + 1) * N_N) / NPART;

    const int lane    = tid & 31;
    const int bq      = tid >> 5;          // 0..7 (b group of 4)
    const int c_local = lane >> 2;         // 0..7
    const int a       = lane & 3;          // e-octet selector: e base = 8*a
    const int swz4    = c_local & 7;
    const int c       = c0 + c_local;
    const int e_base  = 8 * a;

    ull Bv2[4];
    #pragma unroll
    for (int j = 0; j < 4; j++)
        Bv2[j] = fpack2(Bv[c * N_E + e_base + 2 * j],
                        Bv[c * N_E + e_base + 2 * j + 1]);

    ull sacc[4][4];
    #pragma unroll
    for (int i = 0; i < 4; i++)
        #pragma unroll
        for (int j = 0; j < 4; j++) sacc[i][j] = 0ull;

    auto stage = [&](int n, int buf) {
        const float* Wn = W + (size_t)n * (N_C * N_D * N_E) + (size_t)c0 * (N_D * N_E);
        float* Wb = Wsm + buf * 4096;
        #pragma unroll
        for (int k = 0; k < 4; k++) {
            int q = tid + 256 * k;         // float4 index 0..1023
            int p = q * 4;
            int cl = p >> 9;
            int d  = (p >> 5) & 15;
            int e4 = (p & 31) >> 2;
            float* dst = &Wb[cl * 512 + d * 32 + ((e4 ^ (cl & 7)) << 2)];
            cp16(dst, Wn + p);
        }
        if (tid < 128) {
            int b = tid >> 2, dq = tid & 3;
            cp16(&xsm[buf * 512 + b * N_D + dq * 4],
                 x + ((size_t)b * N_N + n) * N_D + dq * 4);
        }
        cp_commit();
    };

    // prologue: two stages in flight (buffers indexed RELATIVE to ns)
    stage(ns, 0);
    if (ns + 1 < ne) stage(ns + 1, 1); else cp_commit();

    int buf = 0;
    for (int n = ns; n < ne; n++) {
        // issue stage n+2 into relative buffer (freed by trailing sync of iter n-1)
        int nxt = n + 2;
        if (nxt < ne) stage(nxt, (nxt - ns) % 3); else cp_commit();
        cp_wait2();                        // group for n retired
        __syncthreads();                   // data for n visible to all

        ull uacc[4][4];
        #pragma unroll
        for (int i = 0; i < 4; i++)
            #pragma unroll
            for (int j = 0; j < 4; j++) uacc[i][j] = 0ull;

        const float* Wrow = Wsm + buf * 4096 + c_local * 512;
        const float* xrow = xsm + buf * 512;
        #pragma unroll
        for (int d = 0; d < N_D; d++) {
            ull xv[4];
            #pragma unroll
            for (int i = 0; i < 4; i++) {
                float xval = xrow[(bq * 4 + i) * N_D + d];
                xv[i] = fpack2(xval, xval);
            }
            int o0 = (((2 * a + 0) ^ swz4) << 2) + d * 32;
            int o1 = (((2 * a + 1) ^ swz4) << 2) + d * 32;
            ulonglong2 w01 = *reinterpret_cast<const ulonglong2*>(Wrow + o0);
            ulonglong2 w23 = *reinterpret_cast<const ulonglong2*>(Wrow + o1);
            ull wv[4] = { w01.x, w01.y, w23.x, w23.y };
            #pragma unroll
            for (int i = 0; i < 4; i++)
                #pragma unroll
                for (int j = 0; j < 4; j++)
                    uacc[i][j] = ffma2(xv[i], wv[j], uacc[i][j]);
        }

        // epilogue: +B, accumulate s1 partial, convert+store fp16 u
        #pragma unroll
        for (int i = 0; i < 4; i++) {
            int b = bq * 4 + i;
            unsigned h[4];
            #pragma unroll
            for (int j = 0; j < 4; j++) {
                ull t = fadd2(uacc[i][j], Bv2[j]);
                sacc[i][j] = fadd2(sacc[i][j], t);
                float2 tf = funpack2(t);
                __half2 hh = __floats2half2_rn(tf.x, tf.y);
                h[j] = reinterpret_cast<unsigned&>(hh);
            }
            size_t uoff = (((size_t)b * N_N + n) * N_C + c) * N_E + e_base;
            *reinterpret_cast<uint4*>(&g_u[uoff]) = make_uint4(h[0], h[1], h[2], h[3]);
        }
        __syncthreads();                   // buf may be restaged next iter
        buf = (buf == 2) ? 0 : buf + 1;
    }

    // write partial sums
    #pragma unroll
    for (int i = 0; i < 4; i++) {
        int b = bq * 4 + i;
        ull* dst = reinterpret_cast<ull*>(
            &g_partials[(size_t)nb * SBCE + ((size_t)b * N_C + c) * N_E + e_base]);
        *reinterpret_cast<ulonglong2*>(dst)     = make_ulonglong2(sacc[i][0], sacc[i][1]);
        *reinterpret_cast<ulonglong2*>(dst + 2) = make_ulonglong2(sacc[i][2], sacc[i][3]);
    }
}

// ---------------------------------------------------------------------------
// Kernel B: routing pass.  logits = u . vsum, coup = softmax_c, s += coup*u
// grid (32 b, 37 n-blocks), 256 threads.  One capsule c per thread, lane-quads.
// ---------------------------------------------------------------------------
__global__ __launch_bounds__(256, 8)
void capsB()
{
    __shared__ __half us[2][N_C * N_E];   // double-buffered u tile (2 x 4KB)
    __shared__ float  wsum[2][8];

    const int tid  = threadIdx.x;
    const int b    = blockIdx.x;
    const int nb   = blockIdx.y;
    const int ns   = (nb * N_N) / NPART;
    const int ne   = ((nb + 1) * N_N) / NPART;
    const int q    = tid & 3;      // e-octet within c
    const int c    = tid >> 2;     // 0..63
    const int lane = tid & 31;
    const int wid  = tid >> 5;

    float vs[8];
    {
        const float4* vp = reinterpret_cast<const float4*>(
            g_vsum + ((size_t)b * N_C + c) * N_E + q * 8);
        float4 v0 = vp[0], v1 = vp[1];
        vs[0] = v0.x; vs[1] = v0.y; vs[2] = v0.z; vs[3] = v0.w;
        vs[4] = v1.x; vs[5] = v1.y; vs[6] = v1.z; vs[7] = v1.w;
    }
    float sacc[8];
    #pragma unroll
    for (int i = 0; i < 8; i++) sacc[i] = 0.0f;

    {
        size_t base = ((size_t)b * N_N + ns) * (N_C * N_E);
        cp16(&us[0][tid * 8], &g_u[base + tid * 8]);
        cp_commit();
    }

    for (int n = ns; n < ne; n++) {
        int cur = (n - ns) & 1;
        if (n + 1 < ne) {
            size_t base = ((size_t)b * N_N + (n + 1)) * (N_C * N_E);
            cp16(&us[cur ^ 1][tid * 8], &g_u[base + tid * 8]);
        }
        cp_commit();
        cp_wait1();
        __syncthreads();   // us[cur] ready, wsum[cur] free

        uint4 raw = *reinterpret_cast<const uint4*>(&us[cur][tid * 8]);
        float2 f0 = __half22float2(reinterpret_cast<__half2&>(raw.x));
        float2 f1 = __half22float2(reinterpret_cast<__half2&>(raw.y));
        float2 f2 = __half22float2(reinterpret_cast<__half2&>(raw.z));
        float2 f3 = __half22float2(reinterpret_cast<__half2&>(raw.w));

        float lp = f0.x * vs[0];
        lp = fmaf(f0.y, vs[1], lp);
        lp = fmaf(f1.x, vs[2], lp);
        lp = fmaf(f1.y, vs[3], lp);
        lp = fmaf(f2.x, vs[4], lp);
        lp = fmaf(f2.y, vs[5], lp);
        lp = fmaf(f3.x, vs[6], lp);
        lp = fmaf(f3.y, vs[7], lp);
        lp += __shfl_xor_sync(0xffffffffu, lp, 1);
        lp += __shfl_xor_sync(0xffffffffu, lp, 2);

        float ex = __expf(lp);
        float s = ex;
        #pragma unroll
        for (int m = 16; m >= 4; m >>= 1)
            s += __shfl_xor_sync(0xffffffffu, s, m);
        s += __shfl_xor_sync(0xffffffffu, s, 2);
        s += __shfl_xor_sync(0xffffffffu, s, 1);
        if (lane == 0) wsum[cur][wid] = s;
        __syncthreads();
        float tot = 0.0f;
        #pragma unroll
        for (int w = 0; w < 8; w++) tot += wsum[cur][w];
        float coup = 4.0f * ex / tot;   // tot counts each c 4x (quad replication)

        sacc[0] = fmaf(coup, f0.x, sacc[0]);
        sacc[1] = fmaf(coup, f0.y, sacc[1]);
        sacc[2] = fmaf(coup, f1.x, sacc[2]);
        sacc[3] = fmaf(coup, f1.y, sacc[3]);
        sacc[4] = fmaf(coup, f2.x, sacc[4]);
        sacc[5] = fmaf(coup, f2.y, sacc[5]);
        sacc[6] = fmaf(coup, f3.x, sacc[6]);
        sacc[7] = fmaf(coup, f3.y, sacc[7]);
    }

    float* dst = &g_partials[(size_t)nb * SBCE + ((size_t)b * N_C + c) * N_E + q * 8];
    *reinterpret_cast<float4*>(dst)     = make_float4(sacc[0], sacc[1], sacc[2], sacc[3]);
    *reinterpret_cast<float4*>(dst + 4) = make_float4(sacc[4], sacc[5], sacc[6], sacc[7]);
}

// ---------------------------------------------------------------------------
// reduce partials (fixed order -> deterministic) + squash; update vsum
// ---------------------------------------------------------------------------
__global__ void reduce_squash(float scale, int overwrite, float* __restrict__ out)
{
    int bc = blockIdx.x;     // b*64 + c
    int e  = threadIdx.x;
    size_t idx = (size_t)bc * N_E + e;
    float s = 0.0f;
    #pragma unroll
    for (int p = 0; p < NPART; p++)
        s += g_partials[(size_t)p * SBCE + idx];
    s *= scale;
    float nsq = s * s;
    #pragma unroll
    for (int m = 16; m >= 1; m >>= 1)
        nsq += __shfl_xor_sync(0xffffffffu, nsq, m);
    float sc = nsq / ((1.0f + nsq) * sqrtf(nsq + 1e-9f));
    float v = sc * s;
    if (overwrite) g_vsum[idx] = v;
    else           g_vsum[idx] += v;
    if (out) out[idx] = v;
}

// ---------------------------------------------------------------------------
extern "C" void kernel_launch(void* const* d_in, const int* in_sizes, int n_in,
                              void* d_out, int out_size)
{
    const float* x  = (const float*)d_in[0];
    const float* W  = (const float*)d_in[1];
    const float* Bv = (const float*)d_in[2];
    float* out = (float*)d_out;

    // idempotent host-side attribute set (no static guard; legal every call)
    cudaFuncSetAttribute(capsA, cudaFuncAttributeMaxDynamicSharedMemorySize,
                         CAPSA_SMEM_BYTES);

    dim3 gA(8, NPART);
    dim3 gB(N_B, NPART);

    capsA<<<gA, 256, CAPSA_SMEM_BYTES>>>(x, W, Bv);
    reduce_squash<<<N_B * N_C, 32>>>(1.0f / 64.0f, 1, nullptr);   // v1 -> vsum
    capsB<<<gB, 256>>>();
    reduce_squash<<<N_B * N_C, 32>>>(1.0f, 0, nullptr);           // vsum += v2
    capsB<<<gB, 256>>>();
    reduce_squash<<<N_B * N_C, 32>>>(1.0f, 0, out);
}